// round 5
// baseline (speedup 1.0000x reference)
#include <cuda_runtime.h>

#define Bq 32
#define Tq 512
#define Dq 128
#define Nq 1024
#define NOISE_C 0.001f
#define GRID_G 128
#define NBG 4            // batch groups
#define NBL 8            // batches per CTA
#define NCOL 32          // columns per CTA
#define NTHR 512
#define NW 16            // warps per CTA
#define KSL 64           // K-slice per warp
#define ITS 16           // KSL/4 float4 iterations

// States double buffer, plain [phase][b][k] layout.
__device__ float g_S[2][Bq][Nq];
// Monotonic arrival counter for the grid barrier. Reset by init_kernel each launch
// (stream-ordered before recur_kernel) -> deterministic & graph-replay-safe.
__device__ unsigned g_count;

struct RecurSmem {
    float Wsm[Nq][NCOL];   // 128 KB
    float red[NW][32][9];  // 18.4 KB, padded
};
#define RECUR_SMEM_BYTES (sizeof(RecurSmem))

// out[:,0,:] = step0 ; unpack states0 into g_S[0] ; reset barrier counter
__global__ void init_kernel(const float* __restrict__ states0,
                            const float* __restrict__ step0,
                            float* __restrict__ out) {
    int i = blockIdx.x * blockDim.x + threadIdx.x;  // 0 .. 32767
    int b = i >> 10;
    int n = i & 1023;
    out[(size_t)b * Tq * Nq + n] = step0[i];
    g_S[0][b][n] = states0[i];
    if (i == 0) g_count = 0u;
}

// xin GEMM: out[b,t,n] = scale * sum_d x[b,t,d] * w_input[d,n]   for t in [1,512)
__global__ __launch_bounds__(256) void xin_gemm(const float* __restrict__ x,
                                                const float* __restrict__ w_in,
                                                const float* __restrict__ scale_p,
                                                float* __restrict__ out) {
    __shared__ float xs[128][33];
    __shared__ float ws[32][132];
    __shared__ int rowoff[128];

    const int tid = threadIdx.x;
    const int tx = tid & 15;
    const int ty = tid >> 4;
    const int bn = blockIdx.x;   // 0..7
    const int bm = blockIdx.y;   // 0..127
    const float sc = *scale_p;

    if (tid < 128) {
        int m = bm * 128 + tid;
        if (m < Bq * (Tq - 1)) {
            int b = m / (Tq - 1);
            int t = m - b * (Tq - 1) + 1;
            rowoff[tid] = (b * Tq + t) * Dq;
        } else {
            rowoff[tid] = -1;
        }
    }

    float acc[8][8];
#pragma unroll
    for (int i = 0; i < 8; ++i)
#pragma unroll
        for (int j = 0; j < 8; ++j) acc[i][j] = 0.f;

    __syncthreads();

    for (int kc = 0; kc < 4; ++kc) {
#pragma unroll
        for (int l = 0; l < 16; ++l) {
            int idx = tid + l * 256;
            int r = idx >> 5, k = idx & 31;
            int ro = rowoff[r];
            xs[r][k] = (ro >= 0) ? x[(size_t)ro + kc * 32 + k] : 0.f;
        }
#pragma unroll
        for (int l = 0; l < 16; ++l) {
            int idx = tid + l * 256;
            int kk = idx >> 7, c = idx & 127;
            ws[kk][c] = w_in[(size_t)(kc * 32 + kk) * Nq + bn * 128 + c];
        }
        __syncthreads();

#pragma unroll
        for (int k = 0; k < 32; ++k) {
            float xr[8], wr[8];
#pragma unroll
            for (int i = 0; i < 8; ++i) xr[i] = xs[ty * 8 + i][k];
#pragma unroll
            for (int j = 0; j < 8; ++j) wr[j] = ws[k][tx * 8 + j];
#pragma unroll
            for (int i = 0; i < 8; ++i)
#pragma unroll
                for (int j = 0; j < 8; ++j) acc[i][j] += xr[i] * wr[j];
        }
        __syncthreads();
    }

#pragma unroll
    for (int i = 0; i < 8; ++i) {
        int ro = rowoff[ty * 8 + i];
        if (ro < 0) continue;
        float* op = out + (size_t)(ro >> 7) * Nq + bn * 128 + tx * 8;
#pragma unroll
        for (int j = 0; j < 8; ++j) op[j] = acc[i][j] * sc;
    }
}

// Persistent recurrence. 2-D split: 128 CTAs = 4 batch-groups x 32 col-groups.
// CTA owns (8 batches x 32 columns); W tile [1024][32] in dynamic SMEM (128 KB).
// Warp w = K-slice [64w, 64w+64); lane = (b_local, col_quad).
// L2 state read traffic: 128 x 32KB = 4 MB/step (was 16 MB).
__global__ __launch_bounds__(NTHR, 1) void recur_kernel(const float* __restrict__ w_res,
                                                        const float* __restrict__ noise,
                                                        float* __restrict__ out) {
    extern __shared__ RecurSmem sm[];
    float (*Wsm)[NCOL] = sm->Wsm;
    float (*red)[32][9] = sm->red;

    const int tid = threadIdx.x;
    const int cta = blockIdx.x;
    const int bg = cta >> 5;           // 0..3
    const int cg = cta & 31;           // 0..31
    const int col0 = cg * NCOL;
    const int b0 = bg * NBL;

    for (int i = tid; i < Nq * NCOL; i += NTHR) {
        int k = i >> 5, c = i & 31;
        Wsm[k][c] = w_res[(size_t)k * Nq + col0 + c];
    }
    __syncthreads();

    const int warp = tid >> 5;
    const int lane = tid & 31;
    const int b_l = lane >> 2;         // 0..7 local batch
    const int cq = lane & 3;           // 0..3 column quad (8 cols each)

    // epilogue mapping (first 256 threads): tid -> (eb 0..7, ec 0..31)
    const bool epi = (tid < NBL * NCOL);
    const int eb = (tid >> 5) & 7;
    const int ec = tid & 31;
    const int gb = b0 + eb;
    const int gc = col0 + ec;
    const float nz = epi ? NOISE_C * noise[gb * Nq + gc] : 0.f;
    float* outp = out + (size_t)gb * Tq * Nq + gc;
    float* sW0 = &g_S[0][gb][gc];
    float* sW1 = &g_S[1][gb][gc];

    const ulonglong2* Wp0 = (const ulonglong2*)&Wsm[warp * KSL][cq * 8];
    unsigned* cnt = &g_count;

    for (int t = 1; t < Tq; ++t) {
        const float4* Sp = (const float4*)&g_S[(t - 1) & 1][b0 + b_l][warp * KSL];

        float xin = epi ? outp[(size_t)t * Nq] : 0.f;  // barrier-independent; issue early

        // fill depth-8 pipeline of L2-only state loads (16 float4 = 64 k)
        float4 buf[8];
#pragma unroll
        for (int j = 0; j < 8; ++j) buf[j] = __ldcg(Sp + j);

        unsigned long long a0 = 0, a1 = 0, a2 = 0, a3 = 0;
        const ulonglong2* wp = Wp0;

#pragma unroll
        for (int it = 0; it < ITS; ++it) {
            float4 s = buf[it & 7];
            if (it < ITS - 8) buf[it & 7] = __ldcg(Sp + it + 8);
#pragma unroll
            for (int kk = 0; kk < 4; ++kk) {
                unsigned sb = __float_as_uint(kk == 0 ? s.x : kk == 1 ? s.y
                                                         : kk == 2 ? s.z : s.w);
                unsigned long long svv;
                asm("mov.b64 %0, {%1, %1};" : "=l"(svv) : "r"(sb));
                ulonglong2 u0 = wp[0];
                ulonglong2 u1 = wp[1];
                wp += 8;   // next k row: 32 floats = 8 ulonglong2
                asm("fma.rn.f32x2 %0, %1, %2, %0;" : "+l"(a0) : "l"(svv), "l"(u0.x));
                asm("fma.rn.f32x2 %0, %1, %2, %0;" : "+l"(a1) : "l"(svv), "l"(u0.y));
                asm("fma.rn.f32x2 %0, %1, %2, %0;" : "+l"(a2) : "l"(svv), "l"(u1.x));
                asm("fma.rn.f32x2 %0, %1, %2, %0;" : "+l"(a3) : "l"(svv), "l"(u1.y));
            }
        }
        wp = Wp0;  // keep register, avoid recompute

        red[warp][lane][0] = __uint_as_float((unsigned)a0);
        red[warp][lane][1] = __uint_as_float((unsigned)(a0 >> 32));
        red[warp][lane][2] = __uint_as_float((unsigned)a1);
        red[warp][lane][3] = __uint_as_float((unsigned)(a1 >> 32));
        red[warp][lane][4] = __uint_as_float((unsigned)a2);
        red[warp][lane][5] = __uint_as_float((unsigned)(a2 >> 32));
        red[warp][lane][6] = __uint_as_float((unsigned)a3);
        red[warp][lane][7] = __uint_as_float((unsigned)(a3 >> 32));
        __syncthreads();

        if (epi) {
            // output (eb, ec): stored at red[w][eb*4 + ec>>3][ec&7]
            const int l = eb * 4 + (ec >> 3);
            const int j = ec & 7;
            float sum = 0.f;
#pragma unroll
            for (int w = 0; w < NW; ++w) sum += red[w][l][j];

            float post = tanhf(sum + xin) + nz;
            outp[(size_t)t * Nq] = post;        // only our own element — safe
            *((t & 1) ? sW1 : sW0) = post;      // next-step state (read via __ldcg)
        }

        // ---- grid barrier: counter arrive (release) + single acquiring poller ----
        __syncthreads();  // all CTA state writes done; HB to thread 0
        if (tid == 0) {
            asm volatile("red.release.gpu.add.u32 [%0], %1;"
                         :: "l"(cnt), "r"(1u) : "memory");
            const unsigned target = (unsigned)GRID_G * (unsigned)t;
            unsigned v;
            do {
                asm volatile("ld.acquire.gpu.u32 %0, [%1];"
                             : "=r"(v) : "l"(cnt) : "memory");
            } while (v < target);
        }
        __syncthreads();  // broadcast completion
    }
}

extern "C" void kernel_launch(void* const* d_in, const int* in_sizes, int n_in,
                              void* d_out, int out_size) {
    (void)in_sizes; (void)n_in; (void)out_size;
    const float* x       = (const float*)d_in[0];
    const float* w_input = (const float*)d_in[1];
    const float* w_res   = (const float*)d_in[2];
    const float* w_scale = (const float*)d_in[3];
    const float* states0 = (const float*)d_in[4];
    const float* step0   = (const float*)d_in[5];
    const float* rnoise  = (const float*)d_in[6];
    float* out = (float*)d_out;

    // idempotent opt-in for >48KB dynamic SMEM (host attr set, capture-legal)
    cudaFuncSetAttribute(recur_kernel, cudaFuncAttributeMaxDynamicSharedMemorySize,
                         (int)RECUR_SMEM_BYTES);

    init_kernel<<<128, 256>>>(states0, step0, out);
    dim3 g(8, 128);
    xin_gemm<<<g, 256>>>(x, w_input, w_scale, out);
    recur_kernel<<<GRID_G, NTHR, RECUR_SMEM_BYTES>>>(w_res, rnoise, out);
}